// round 14
// baseline (speedup 1.0000x reference)
#include <cuda_runtime.h>
#include <cstdint>
#include <math.h>

// Problem constants
#define BQ   4096   // batch
#define SDIM 2048   // state size
#define FDIM 2048   // feature size
#define KDIM 4096   // S + F
#define NDIM 6144   // 3 * S
#define KX2  8192   // concatenated slice stride (A1|A2), (B2|B1)

// ---------------- device scratch (static; no runtime allocation) -------------
__device__ int8_t   g_X8[(size_t)BQ * KX2];    // 32 MB: [m][0:4096]=A1, [4096:]=A2
__device__ int8_t   g_W8[(size_t)NDIM * KX2];  // 48 MB: [n][0:4096]=B2, [4096:]=B1
__device__ float    g_sx[BQ];                  // per-row max |x|
__device__ unsigned g_swu[NDIM];               // per-col max |w| (float bits)
__device__ float    g_gates[(size_t)BQ * NDIM];// 96 MB

// ---------------- helpers ----------------------------------------------------
__device__ __forceinline__ void cp16(void* smem, const void* gmem) {
    unsigned sa = (unsigned)__cvta_generic_to_shared(smem);
    asm volatile("cp.async.cg.shared.global [%0], [%1], 16;\n" :: "r"(sa), "l"(gmem));
}
__device__ __forceinline__ void cp_commit() {
    asm volatile("cp.async.commit_group;\n" ::: "memory");
}
__device__ __forceinline__ void cp_wait1() {
    asm volatile("cp.async.wait_group 1;\n" ::: "memory");
}
__device__ __forceinline__ void ldmx4(unsigned* r, unsigned addr) {
    asm volatile("ldmatrix.sync.aligned.m8n8.x4.shared.b16 {%0,%1,%2,%3}, [%4];"
                 : "=r"(r[0]), "=r"(r[1]), "=r"(r[2]), "=r"(r[3]) : "r"(addr));
}
// int8 MMA, k32, s32 accumulate: 2x MACs/instr vs bf16 k16
__device__ __forceinline__ void mma_s8(int* c, const unsigned* a,
                                       unsigned b0, unsigned b1) {
    asm volatile(
        "mma.sync.aligned.m16n8k32.row.col.s32.s8.s8.s32 "
        "{%0,%1,%2,%3}, {%4,%5,%6,%7}, {%8,%9}, {%0,%1,%2,%3};\n"
        : "+r"(c[0]), "+r"(c[1]), "+r"(c[2]), "+r"(c[3])
        : "r"(a[0]), "r"(a[1]), "r"(a[2]), "r"(a[3]), "r"(b0), "r"(b1));
}

// ---------------- kernel 1: quantize X = [old_h | input] to 2 int8 slices ----
__global__ void quant_x_kernel(const float* __restrict__ old_h,
                               const float* __restrict__ input) {
    __shared__ float xb[KDIM];
    __shared__ float red[256];
    int m = blockIdx.x, tid = threadIdx.x;
    float mx = 0.0f;
    #pragma unroll
    for (int j = 0; j < KDIM / 256; j++) {
        int k = tid + j * 256;
        float v = (k < SDIM) ? old_h[(size_t)m * SDIM + k]
                             : input[(size_t)m * FDIM + (k - SDIM)];
        xb[k] = v;
        mx = fmaxf(mx, fabsf(v));
    }
    red[tid] = mx;
    __syncthreads();
    for (int s = 128; s > 0; s >>= 1) {
        if (tid < s) red[tid] = fmaxf(red[tid], red[tid + s]);
        __syncthreads();
    }
    float rmax = red[0];
    if (tid == 0) g_sx[m] = rmax;
    float inv = (rmax > 0.0f) ? 127.0f / rmax : 0.0f;
    #pragma unroll
    for (int j = 0; j < KDIM / 256; j++) {
        int k = tid + j * 256;
        float xs = xb[k] * inv;
        int a1 = __float2int_rn(xs);
        float r = xs - (float)a1;
        int a2 = max(-127, min(127, __float2int_rn(r * 256.0f)));
        g_X8[(size_t)m * KX2 + k]        = (int8_t)a1;
        g_X8[(size_t)m * KX2 + KDIM + k] = (int8_t)a2;
    }
}

// ---------------- kernels 2a/2b: per-column |W| max --------------------------
__global__ void zero_sw_kernel() {
    int n = blockIdx.x * 256 + threadIdx.x;
    if (n < NDIM) g_swu[n] = 0u;
}
__global__ void wmax_kernel(const float* __restrict__ W) {
    int n  = blockIdx.x * 256 + threadIdx.x;   // 24 blocks over N
    int k0 = blockIdx.y * 256;                 // 16 K-chunks
    float mx = 0.0f;
    for (int j = 0; j < 256; j++)
        mx = fmaxf(mx, fabsf(W[(size_t)(k0 + j) * NDIM + n]));
    atomicMax(&g_swu[n], __float_as_uint(mx));  // nonneg floats: bit-order == value-order
}

// ---------------- kernel 3: transpose + quantize W to 2 int8 slices ----------
__global__ void quant_w_kernel(const float* __restrict__ W) {
    __shared__ float tile[32][33];
    int n0 = blockIdx.x * 32;
    int k0 = blockIdx.y * 32;
    int tx = threadIdx.x;   // 0..31
    int ty = threadIdx.y;   // 0..7
    #pragma unroll
    for (int j = 0; j < 4; j++) {
        int k = ty + j * 8;
        tile[k][tx] = W[(size_t)(k0 + k) * NDIM + n0 + tx];
    }
    __syncthreads();
    #pragma unroll
    for (int j = 0; j < 4; j++) {
        int nl = ty + j * 8;
        int n = n0 + nl;
        float rmax = __uint_as_float(g_swu[n]);
        float inv = (rmax > 0.0f) ? 127.0f / rmax : 0.0f;
        float ws = tile[tx][nl] * inv;
        int b1 = __float2int_rn(ws);
        float r = ws - (float)b1;
        int b2 = max(-127, min(127, __float2int_rn(r * 256.0f)));
        g_W8[(size_t)n * KX2 + KDIM + (k0 + tx)] = (int8_t)b1;  // B1 in back half
        g_W8[(size_t)n * KX2 + (k0 + tx)]        = (int8_t)b2;  // B2 in front half
    }
}

// ---------------- kernel 4: int8 GEMM (m16n8k32, s32 accum) ------------------
// CTA tile 128(M) x 256(N), K-stage 128 bytes, 3-stage cp.async ring.
// 8 warps 2(M) x 4(N), warp tile 64x64. ldmatrix.x4 (b16 view == s8 frags).
// Row stride 144 B: ldmatrix phases & cp.async writes bank-conflict-free.
#define KT 128
#define RS 144
#define A_ST (128 * RS)
#define B_ST (256 * RS)
#define GSMEM (3 * (A_ST + B_ST))   // 165888 bytes

__global__ __launch_bounds__(256) void int8_gemm_kernel(int ka, int kb, int klen,
                                                        int accumulate, float wfac) {
    extern __shared__ int8_t smem[];
    int8_t* As = smem;
    int8_t* Bs = smem + 3 * A_ST;

    const int tid  = threadIdx.x;
    const int warp = tid >> 5, lane = tid & 31;
    const int wm = warp >> 2, wn = warp & 3;
    const int g  = lane >> 2, tig = lane & 3;
    const int m0 = blockIdx.y * 128;
    const int n0 = blockIdx.x * 256;

    int acc[4][8][4];
    #pragma unroll
    for (int mi = 0; mi < 4; mi++)
        #pragma unroll
        for (int ni = 0; ni < 8; ni++)
            #pragma unroll
            for (int r = 0; r < 4; r++) acc[mi][ni][r] = 0;

    const int NUM = klen / KT;

    auto load_stage = [&](int t) {
        int buf = t % 3;
        int kk = t * KT;
        int8_t* Ab = As + buf * A_ST;
        int8_t* Bb = Bs + buf * B_ST;
        #pragma unroll
        for (int i = 0; i < 4; i++) {         // A: 128 rows x 8 chunks of 16B
            int id = tid + i * 256;
            int row = id >> 3;
            int kc = (id & 7) << 4;
            cp16(Ab + row * RS + kc, g_X8 + (size_t)(m0 + row) * KX2 + ka + kk + kc);
        }
        #pragma unroll
        for (int i = 0; i < 8; i++) {         // B: 256 rows x 8 chunks
            int id = tid + i * 256;
            int row = id >> 3;
            int kc = (id & 7) << 4;
            cp16(Bb + row * RS + kc, g_W8 + (size_t)(n0 + row) * KX2 + kb + kk + kc);
        }
        cp_commit();
    };

    load_stage(0);
    load_stage(1);

    const int lrow = lane & 15;
    const int lk16 = (lane >> 4) * 16;        // byte offset within 32B k-chunk

    for (int t = 0; t < NUM; t++) {
        cp_wait1();
        __syncthreads();
        if (t + 2 < NUM) load_stage(t + 2);

        int buf = t % 3;
        const int8_t* Ab = As + buf * A_ST;
        const int8_t* Bb = Bs + buf * B_ST;
        const int arow = wm * 64 + lrow;
        const int brow = wn * 64 + lrow;

        #pragma unroll
        for (int kh = 0; kh < 4; kh++) {      // 4 x k32 per 128B stage
            int kb0 = kh * 32 + lk16;
            unsigned af[4][4], bf[4][4];
            #pragma unroll
            for (int mi = 0; mi < 4; mi++)
                ldmx4(af[mi], (unsigned)__cvta_generic_to_shared(
                          Ab + (arow + mi * 16) * RS + kb0));
            #pragma unroll
            for (int nj = 0; nj < 4; nj++)
                ldmx4(bf[nj], (unsigned)__cvta_generic_to_shared(
                          Bb + (brow + nj * 16) * RS + kb0));
            #pragma unroll
            for (int mi = 0; mi < 4; mi++) {
                #pragma unroll
                for (int nj = 0; nj < 4; nj++) {
                    mma_s8(acc[mi][2 * nj],     af[mi], bf[nj][0], bf[nj][2]);
                    mma_s8(acc[mi][2 * nj + 1], af[mi], bf[nj][1], bf[nj][3]);
                }
            }
        }
    }

    // epilogue: scale by sx*sw/(127^2)*wfac, store or accumulate
    const float cfac = wfac / (127.0f * 127.0f);
    #pragma unroll
    for (int mi = 0; mi < 4; mi++) {
        int row = m0 + wm * 64 + mi * 16 + g;
        float sa0 = g_sx[row] * cfac;
        float sa1 = g_sx[row + 8] * cfac;
        #pragma unroll
        for (int ni = 0; ni < 8; ni++) {
            int col = n0 + wn * 64 + ni * 8 + 2 * tig;
            float sw0 = __uint_as_float(g_swu[col]);
            float sw1 = __uint_as_float(g_swu[col + 1]);
            float v0 = (float)acc[mi][ni][0] * sa0 * sw0;
            float v1 = (float)acc[mi][ni][1] * sa0 * sw1;
            float v2 = (float)acc[mi][ni][2] * sa1 * sw0;
            float v3 = (float)acc[mi][ni][3] * sa1 * sw1;
            float* p0 = &g_gates[(size_t)row * NDIM + col];
            float* p1 = &g_gates[(size_t)(row + 8) * NDIM + col];
            if (accumulate) {
                float2 o0 = *(float2*)p0, o1 = *(float2*)p1;
                *(float2*)p0 = make_float2(o0.x + v0, o0.y + v1);
                *(float2*)p1 = make_float2(o1.x + v2, o1.y + v3);
            } else {
                *(float2*)p0 = make_float2(v0, v1);
                *(float2*)p1 = make_float2(v2, v3);
            }
        }
    }
}

// ---------------- kernel 5: fused LLTM epilogue (vectorized x4) --------------
__global__ void lltm_epilogue_kernel(const float* __restrict__ bias,
                                     const float* __restrict__ old_c,
                                     float* __restrict__ out) {
    size_t i4 = (size_t)blockIdx.x * 256 + threadIdx.x;  // over BQ*SDIM/4
    size_t i = i4 * 4;
    int b = (int)(i >> 11);
    int s = (int)(i & 2047);
    size_t base = (size_t)b * NDIM + s;

    float4 gi4 = *(const float4*)&g_gates[base];
    float4 go4 = *(const float4*)&g_gates[base + SDIM];
    float4 gc4 = *(const float4*)&g_gates[base + 2 * SDIM];
    float4 bi4 = *(const float4*)&bias[s];
    float4 bo4 = *(const float4*)&bias[SDIM + s];
    float4 bc4 = *(const float4*)&bias[2 * SDIM + s];
    float4 oc4 = *(const float4*)&old_c[i];

    float nh[4], nc[4];
    float gis[4] = {gi4.x + bi4.x, gi4.y + bi4.y, gi4.z + bi4.z, gi4.w + bi4.w};
    float gos[4] = {go4.x + bo4.x, go4.y + bo4.y, go4.z + bo4.z, go4.w + bo4.w};
    float gcs[4] = {gc4.x + bc4.x, gc4.y + bc4.y, gc4.z + bc4.z, gc4.w + bc4.w};
    float ocs[4] = {oc4.x, oc4.y, oc4.z, oc4.w};
    #pragma unroll
    for (int j = 0; j < 4; j++) {
        float ig = 1.0f / (1.0f + __expf(-gis[j]));
        float og = 1.0f / (1.0f + __expf(-gos[j]));
        float cand = (gcs[j] > 0.0f) ? gcs[j] : expm1f(gcs[j]);
        nc[j] = ocs[j] + cand * ig;
        nh[j] = tanhf(nc[j]) * og;
    }
    *(float4*)&out[i] = make_float4(nh[0], nh[1], nh[2], nh[3]);
    *(float4*)&out[(size_t)BQ * SDIM + i] = make_float4(nc[0], nc[1], nc[2], nc[3]);
}

// ---------------- launch ------------------------------------------------------
extern "C" void kernel_launch(void* const* d_in, const int* in_sizes, int n_in,
                              void* d_out, int out_size) {
    const float* weights = (const float*)d_in[0];
    const float* bias    = (const float*)d_in[1];
    const float* input   = (const float*)d_in[2];
    const float* old_h   = (const float*)d_in[3];
    const float* old_c   = (const float*)d_in[4];
    float* out = (float*)d_out;
    (void)in_sizes; (void)n_in; (void)out_size;

    cudaFuncSetAttribute(int8_gemm_kernel,
                         cudaFuncAttributeMaxDynamicSharedMemorySize, GSMEM);

    // 1. quantize X (per-row scale, 2 slices)
    quant_x_kernel<<<BQ, 256>>>(old_h, input);

    // 2. per-column |W| max, then transpose+quantize W (2 slices)
    zero_sw_kernel<<<NDIM / 256, 256>>>();
    wmax_kernel<<<dim3(NDIM / 256, KDIM / 256), 256>>>(weights);
    {
        dim3 tb(32, 8);
        dim3 tg(NDIM / 32, KDIM / 32);
        quant_w_kernel<<<tg, tb>>>(weights);
    }

    dim3 gg(NDIM / 256, BQ / 128);   // (24, 32)
    // 3a. main term: A1 (offset 0) x B1 (offset 4096), K=4096
    int8_gemm_kernel<<<gg, 256, GSMEM>>>(0, KDIM, KDIM, 0, 1.0f);
    // 3b. cross terms: [A1|A2] x [B2;B1], K=8192, weight 1/256, accumulate
    int8_gemm_kernel<<<gg, 256, GSMEM>>>(0, 0, KX2, 1, 1.0f / 256.0f);

    // 4. epilogue
    lltm_epilogue_kernel<<<(BQ * (size_t)SDIM) / 1024, 256>>>(bias, old_c, out);
}

// round 15
// speedup vs baseline: 1.4520x; 1.4520x over previous
#include <cuda_runtime.h>
#include <cuda_bf16.h>
#include <cstdint>
#include <math.h>

// Problem constants
#define BQ   4096   // batch
#define SDIM 2048   // state size
#define FDIM 2048   // feature size
#define KDIM 4096   // S + F
#define NDIM 6144   // 3 * S

// ---------------- device scratch (static; no runtime allocation) -------------
__device__ __nv_bfloat16 g_Xhi[(size_t)BQ * KDIM];     // 32 MB
__device__ __nv_bfloat16 g_Xlo[(size_t)BQ * KDIM];     // 32 MB
__device__ float         g_Xf [(size_t)BQ * KDIM];     // 64 MB (fp32 X for FFMA warps)
__device__ __nv_bfloat16 g_WThi[(size_t)NDIM * KDIM];  // 48 MB (W^T [N][K])
__device__ __nv_bfloat16 g_WTlo[(size_t)NDIM * KDIM];  // 48 MB
__device__ float         g_WTf [(size_t)NDIM * KDIM];  // 96 MB (fp32 W^T)
__device__ float         g_gates[(size_t)BQ * NDIM];   // 96 MB

// ---------------- helpers ----------------------------------------------------
__device__ __forceinline__ void cp16(void* smem, const void* gmem) {
    unsigned sa = (unsigned)__cvta_generic_to_shared(smem);
    asm volatile("cp.async.cg.shared.global [%0], [%1], 16;\n" :: "r"(sa), "l"(gmem));
}
__device__ __forceinline__ void cp_commit() {
    asm volatile("cp.async.commit_group;\n" ::: "memory");
}
__device__ __forceinline__ void cp_wait1() {
    asm volatile("cp.async.wait_group 1;\n" ::: "memory");
}
__device__ __forceinline__ void ldmx4(unsigned* r, unsigned addr) {
    asm volatile("ldmatrix.sync.aligned.m8n8.x4.shared.b16 {%0,%1,%2,%3}, [%4];"
                 : "=r"(r[0]), "=r"(r[1]), "=r"(r[2]), "=r"(r[3]) : "r"(addr));
}
__device__ __forceinline__ void mma_bf16(float* c, const unsigned* a,
                                         unsigned b0, unsigned b1) {
    asm volatile(
        "mma.sync.aligned.m16n8k16.row.col.f32.bf16.bf16.f32 "
        "{%0,%1,%2,%3}, {%4,%5,%6,%7}, {%8,%9}, {%0,%1,%2,%3};\n"
        : "+f"(c[0]), "+f"(c[1]), "+f"(c[2]), "+f"(c[3])
        : "r"(a[0]), "r"(a[1]), "r"(a[2]), "r"(a[3]), "r"(b0), "r"(b1));
}
// Blackwell packed fp32 FMA: d.xy = a.xy * b.xy + d.xy (2 FMA/lane/instr)
__device__ __forceinline__ void ffma2(float2& d, float2 a, float2 b) {
    unsigned long long du = *(unsigned long long*)&d;
    unsigned long long au = *(unsigned long long*)&a;
    unsigned long long bu = *(unsigned long long*)&b;
    asm("fma.rn.f32x2 %0, %1, %2, %0;" : "+l"(du) : "l"(au), "l"(bu));
    d = *(float2*)&du;
}
#define BAR_T() asm volatile("bar.sync 1, 256;" ::: "memory")
#define BAR_F() asm volatile("bar.sync 2, 128;" ::: "memory")

// ---------------- kernel 1: X = [old_h | input]: bf16 hi/lo + fp32 -----------
__global__ void split_x_kernel(const float* __restrict__ old_h,
                               const float* __restrict__ input) {
    size_t i = (size_t)blockIdx.x * 256 + threadIdx.x;   // over BQ*KDIM
    int b = (int)(i >> 12);
    int k = (int)(i & 4095);
    float x = (k < SDIM) ? old_h[(size_t)b * SDIM + k]
                         : input[(size_t)b * FDIM + (k - SDIM)];
    __nv_bfloat16 hi = __float2bfloat16(x);
    g_Xhi[i] = hi;
    g_Xlo[i] = __float2bfloat16(x - __bfloat162float(hi));
    g_Xf[i]  = x;
}

// ---------------- kernel 2: W [K][N] -> WT [N][K]: bf16 hi/lo + fp32 ---------
__global__ void split_wt_kernel(const float* __restrict__ weights) {
    __shared__ float tile[32][33];
    int n0 = blockIdx.x * 32;
    int k0 = blockIdx.y * 32;
    int tx = threadIdx.x;   // 0..31
    int ty = threadIdx.y;   // 0..7
    #pragma unroll
    for (int j = 0; j < 4; j++) {
        int k = ty + j * 8;
        tile[k][tx] = weights[(size_t)(k0 + k) * NDIM + n0 + tx];
    }
    __syncthreads();
    #pragma unroll
    for (int j = 0; j < 4; j++) {
        int nl = ty + j * 8;
        float v = tile[tx][nl];
        __nv_bfloat16 hi = __float2bfloat16(v);
        size_t dst = (size_t)(n0 + nl) * KDIM + (k0 + tx);
        g_WThi[dst] = hi;
        g_WTlo[dst] = __float2bfloat16(v - __bfloat162float(hi));
        g_WTf[dst]  = v;
    }
}

// ---------------- kernel 3: hybrid GEMM ---------------------------------------
// Each CTA (384 threads) computes a 128(M) x 192(N) gates tile:
//   warps 0-7  (256 thr): cols [nb, nb+128)  via bf16x3 HMMA (tensor pipe)
//   warps 8-11 (128 thr): cols [nb+128, nb+192) via fp32 FFMA2 (fma pipe)
// The two groups share no smem and sync only within their own named barrier.
#define RS 72                           // bf16 row stride (144 B, conflict-free)
#define A_ST (128 * RS)
#define B_ST (128 * RS)
#define TENS_BYTES (3 * (A_ST + B_ST) * 2)          // 110592
#define FF_A_OFF TENS_BYTES                          // Af[32][256] fp32 (dup-packed)
#define FF_B_OFF (TENS_BYTES + 32 * 256 * 4)         // Bf[32][68]  fp32
#define HYB_SMEM (FF_B_OFF + 32 * 68 * 4)            // 152064 bytes

__global__ __launch_bounds__(384, 1) void hybrid_gemm_kernel() {
    extern __shared__ char smem[];
    const int tid = threadIdx.x;
    const int m0 = blockIdx.y * 128;
    const int nb = blockIdx.x * 192;

    if (tid < 256) {
        // ================= tensor group: bf16x3, cols [nb, nb+128) ===========
        __nv_bfloat16* As = (__nv_bfloat16*)smem;
        __nv_bfloat16* Bs = (__nv_bfloat16*)smem + 3 * A_ST;
        const int warp = tid >> 5, lane = tid & 31;
        const int wm = warp >> 2, wn = warp & 3;     // 2(M) x 4(N); warp 64x32
        const int g = lane >> 2, tig = lane & 3;

        float acc[4][4][4];
        #pragma unroll
        for (int mi = 0; mi < 4; mi++)
            #pragma unroll
            for (int ni = 0; ni < 4; ni++)
                #pragma unroll
                for (int r = 0; r < 4; r++) acc[mi][ni][r] = 0.0f;

        auto load_stage = [&](int t) {
            int seg = t >> 6;                         // 64 stages / segment
            int kk = (t & 63) << 6;
            const __nv_bfloat16* Ap = (seg == 1) ? g_Xlo : g_Xhi;
            const __nv_bfloat16* Bp = (seg == 2) ? g_WTlo : g_WThi;
            int buf = t % 3;
            __nv_bfloat16* Ab = As + buf * A_ST;
            __nv_bfloat16* Bb = Bs + buf * B_ST;
            #pragma unroll
            for (int i = 0; i < 4; i++) {             // A: 128 rows x 8 chunks
                int id = tid + i * 256;
                int row = id >> 3;
                int kc = (id & 7) << 3;
                cp16(&Ab[row * RS + kc], Ap + (size_t)(m0 + row) * KDIM + kk + kc);
            }
            #pragma unroll
            for (int i = 0; i < 4; i++) {             // B: 128 rows x 8 chunks
                int id = tid + i * 256;
                int row = id >> 3;
                int kc = (id & 7) << 3;
                cp16(&Bb[row * RS + kc], Bp + (size_t)(nb + row) * KDIM + kk + kc);
            }
            cp_commit();
        };

        load_stage(0);
        load_stage(1);

        const int lrow = lane & 15;
        const int lkof = (lane >> 4) * 8;

        for (int t = 0; t < 192; t++) {
            cp_wait1();
            BAR_T();
            if (t + 2 < 192) load_stage(t + 2);

            int buf = t % 3;
            const __nv_bfloat16* Ab = As + buf * A_ST;
            const __nv_bfloat16* Bb = Bs + buf * B_ST;
            const int arow = wm * 64 + lrow;
            const int brow = wn * 32 + lrow;

            #pragma unroll
            for (int kh = 0; kh < 4; kh++) {
                int k0 = kh * 16 + lkof;
                unsigned af[4][4], bf[2][4];
                #pragma unroll
                for (int mi = 0; mi < 4; mi++)
                    ldmx4(af[mi], (unsigned)__cvta_generic_to_shared(
                              &Ab[(arow + mi * 16) * RS + k0]));
                #pragma unroll
                for (int nj = 0; nj < 2; nj++)
                    ldmx4(bf[nj], (unsigned)__cvta_generic_to_shared(
                              &Bb[(brow + nj * 16) * RS + k0]));
                #pragma unroll
                for (int mi = 0; mi < 4; mi++) {
                    #pragma unroll
                    for (int nj = 0; nj < 2; nj++) {
                        mma_bf16(acc[mi][2 * nj],     af[mi], bf[nj][0], bf[nj][2]);
                        mma_bf16(acc[mi][2 * nj + 1], af[mi], bf[nj][1], bf[nj][3]);
                    }
                }
            }
        }

        #pragma unroll
        for (int mi = 0; mi < 4; mi++) {
            #pragma unroll
            for (int ni = 0; ni < 4; ni++) {
                int row = m0 + wm * 64 + mi * 16 + g;
                int col = nb + wn * 32 + ni * 8 + 2 * tig;
                *(float2*)&g_gates[(size_t)row * NDIM + col] =
                    make_float2(acc[mi][ni][0], acc[mi][ni][1]);
                *(float2*)&g_gates[(size_t)(row + 8) * NDIM + col] =
                    make_float2(acc[mi][ni][2], acc[mi][ni][3]);
            }
        }
    } else {
        // ================= FFMA group: fp32, cols [nb+128, nb+192) ===========
        float* Af = (float*)(smem + FF_A_OFF);        // [32][256] dup-packed
        float* Bf = (float*)(smem + FF_B_OFF);        // [32][68]
        const int wt = tid - 256;                     // 0..127
        const int tx = wt & 7;                        // 8 N-groups of 8
        const int ty = wt >> 3;                       // 16 M-groups of 8
        const int nf0 = nb + 128;
        const int bn = wt & 63;                       // B row (col of gates)
        const int bkh = (wt >> 6) * 16;               // B k-half within stage

        float2 acc2[8][4];
        #pragma unroll
        for (int i = 0; i < 8; i++)
            #pragma unroll
            for (int j = 0; j < 4; j++) acc2[i][j] = make_float2(0.0f, 0.0f);

        const float* Agp = g_Xf + (size_t)(m0 + wt) * KDIM;
        const float* Bgp = g_WTf + (size_t)(nf0 + bn) * KDIM + bkh;

        float4 ar[8], br[4];
        #pragma unroll
        for (int j = 0; j < 8; j++) ar[j] = *(const float4*)(Agp + j * 4);
        #pragma unroll
        for (int j = 0; j < 4; j++) br[j] = *(const float4*)(Bgp + j * 4);

        for (int t = 0; t < 128; t++) {               // K/32 stages
            BAR_F();                                  // prior reads done
            // store A duplicated: Af[k][2m]=Af[k][2m+1]=A[m][k]
            #pragma unroll
            for (int j = 0; j < 8; j++) {
                const float* av = (const float*)&ar[j];
                #pragma unroll
                for (int e = 0; e < 4; e++)
                    *(float2*)&Af[(j * 4 + e) * 256 + 2 * wt] =
                        make_float2(av[e], av[e]);
            }
            // store B transposed: Bf[k][n]
            #pragma unroll
            for (int j = 0; j < 4; j++) {
                const float* bv = (const float*)&br[j];
                #pragma unroll
                for (int e = 0; e < 4; e++)
                    Bf[(bkh + j * 4 + e) * 68 + bn] = bv[e];
            }
            BAR_F();                                  // stores visible
            if (t + 1 < 128) {                        // prefetch next stage
                int kk = (t + 1) * 32;
                #pragma unroll
                for (int j = 0; j < 8; j++) ar[j] = *(const float4*)(Agp + kk + j * 4);
                #pragma unroll
                for (int j = 0; j < 4; j++) br[j] = *(const float4*)(Bgp + kk + j * 4);
            }
            #pragma unroll
            for (int k = 0; k < 32; k++) {
                float4 a01 = *(const float4*)&Af[k * 256 + ty * 16];
                float4 a23 = *(const float4*)&Af[k * 256 + ty * 16 + 4];
                float4 a45 = *(const float4*)&Af[k * 256 + ty * 16 + 8];
                float4 a67 = *(const float4*)&Af[k * 256 + ty * 16 + 12];
                float4 b03 = *(const float4*)&Bf[k * 68 + tx * 8];
                float4 b47 = *(const float4*)&Bf[k * 68 + tx * 8 + 4];
                float2 ap[8] = {
                    make_float2(a01.x, a01.y), make_float2(a01.z, a01.w),
                    make_float2(a23.x, a23.y), make_float2(a23.z, a23.w),
                    make_float2(a45.x, a45.y), make_float2(a45.z, a45.w),
                    make_float2(a67.x, a67.y), make_float2(a67.z, a67.w)};
                float2 bp[4] = {
                    make_float2(b03.x, b03.y), make_float2(b03.z, b03.w),
                    make_float2(b47.x, b47.y), make_float2(b47.z, b47.w)};
                #pragma unroll
                for (int i = 0; i < 8; i++)
                    #pragma unroll
                    for (int jp = 0; jp < 4; jp++)
                        ffma2(acc2[i][jp], ap[i], bp[jp]);
            }
        }

        #pragma unroll
        for (int i = 0; i < 8; i++) {
            int row = m0 + ty * 8 + i;
            #pragma unroll
            for (int jp = 0; jp < 4; jp++) {
                int col = nf0 + tx * 8 + 2 * jp;
                *(float2*)&g_gates[(size_t)row * NDIM + col] = acc2[i][jp];
            }
        }
    }
}

// ---------------- kernel 4: fused LLTM epilogue (vectorized x4) --------------
__global__ void lltm_epilogue_kernel(const float* __restrict__ bias,
                                     const float* __restrict__ old_c,
                                     float* __restrict__ out) {
    size_t i4 = (size_t)blockIdx.x * 256 + threadIdx.x;  // over BQ*SDIM/4
    size_t i = i4 * 4;
    int b = (int)(i >> 11);
    int s = (int)(i & 2047);
    size_t base = (size_t)b * NDIM + s;

    float4 gi4 = *(const float4*)&g_gates[base];
    float4 go4 = *(const float4*)&g_gates[base + SDIM];
    float4 gc4 = *(const float4*)&g_gates[base + 2 * SDIM];
    float4 bi4 = *(const float4*)&bias[s];
    float4 bo4 = *(const float4*)&bias[SDIM + s];
    float4 bc4 = *(const float4*)&bias[2 * SDIM + s];
    float4 oc4 = *(const float4*)&old_c[i];

    float nh[4], nc[4];
    float gis[4] = {gi4.x + bi4.x, gi4.y + bi4.y, gi4.z + bi4.z, gi4.w + bi4.w};
    float gos[4] = {go4.x + bo4.x, go4.y + bo4.y, go4.z + bo4.z, go4.w + bo4.w};
    float gcs[4] = {gc4.x + bc4.x, gc4.y + bc4.y, gc4.z + bc4.z, gc4.w + bc4.w};
    float ocs[4] = {oc4.x, oc4.y, oc4.z, oc4.w};
    #pragma unroll
    for (int j = 0; j < 4; j++) {
        float ig = 1.0f / (1.0f + __expf(-gis[j]));
        float og = 1.0f / (1.0f + __expf(-gos[j]));
        float cand = (gcs[j] > 0.0f) ? gcs[j] : expm1f(gcs[j]);
        nc[j] = ocs[j] + cand * ig;
        nh[j] = tanhf(nc[j]) * og;
    }
    *(float4*)&out[i] = make_float4(nh[0], nh[1], nh[2], nh[3]);
    *(float4*)&out[(size_t)BQ * SDIM + i] = make_float4(nc[0], nc[1], nc[2], nc[3]);
}

// ---------------- launch ------------------------------------------------------
extern "C" void kernel_launch(void* const* d_in, const int* in_sizes, int n_in,
                              void* d_out, int out_size) {
    const float* weights = (const float*)d_in[0];
    const float* bias    = (const float*)d_in[1];
    const float* input   = (const float*)d_in[2];
    const float* old_h   = (const float*)d_in[3];
    const float* old_c   = (const float*)d_in[4];
    float* out = (float*)d_out;
    (void)in_sizes; (void)n_in; (void)out_size;

    cudaFuncSetAttribute(hybrid_gemm_kernel,
                         cudaFuncAttributeMaxDynamicSharedMemorySize, HYB_SMEM);

    // 1. X = [old_h | input]: bf16 hi/lo + fp32
    split_x_kernel<<<(BQ * (size_t)KDIM) / 256, 256>>>(old_h, input);

    // 2. W -> WT [N][K]: bf16 hi/lo + fp32
    {
        dim3 tb(32, 8);
        dim3 tg(NDIM / 32, KDIM / 32);
        split_wt_kernel<<<tg, tb>>>(weights);
    }

    // 3. hybrid GEMM: tensor pipe (bf16x3) + fma pipe (fp32x2) per CTA
    {
        dim3 gg(NDIM / 192, BQ / 128);   // (32, 32)
        hybrid_gemm_kernel<<<gg, 384, HYB_SMEM>>>();
    }

    // 4. epilogue
    lltm_epilogue_kernel<<<(BQ * (size_t)SDIM) / 1024, 256>>>(bias, old_c, out);
}